// round 15
// baseline (speedup 1.0000x reference)
#include <cuda_runtime.h>
#include <cuda_fp16.h>
#include <cstdint>

// B=64, C=1, T=1024, N=512.
// corr[b] = normalized column-centered Gram of x[b,0] (T x N). BN cancels.
// G[n,m] = sum_t x[t,n]x[t,m] - T*mu[n]*mu[m];  corr = clip(G*invd_n*invd_m)
// fp16 split x = h + l; 2-pass MMA: G_ij ~= h_i h_j^T + h_i l_j^T (fp16 acc),
// mirror write carries the transposed correction -> symmetric output.
// R15: BK=128 (8 chunks, half the syncs of R14, 2x delivery window),
// 2-stage cp.async ring (204KB smem), fragment double-buffering.

#define BB 64
#define TT 1024
#define NN 512
#define NT 4            // 512/128 tiles
#define NPAIRS_TC 10    // upper-triangular tile pairs
#define BK 128          // K-chunk
#define NCHUNK (TT / BK)           // 8
#define PITCH 136       // fp16 per smem row (conflict-free for ldsm)
#define COMP_E (BK * PITCH)        // 17408 elements per component
#define STAGE_E (3 * COMP_E)       // Ahi, Bhi, Blo
#define NSTAGE 2
#define DYN_B (NSTAGE * STAGE_E * 2)   // 208896 bytes

__device__ __half g_hi[(size_t)BB * TT * NN];
__device__ __half g_lo[(size_t)BB * TT * NN];
__device__ float g_mu[BB * NN];
__device__ float g_invd[BB * NN];

__device__ __forceinline__ uint32_t h2u(__half2 h) {
    return *reinterpret_cast<uint32_t*>(&h);
}

// ---------------------------------------------------------------------------
// Kernel 1: convert fp32 -> (hi, lo) fp16 + column stats. Pure streaming.
// ---------------------------------------------------------------------------
__global__ __launch_bounds__(256) void convert_stats(const float* __restrict__ x) {
    __shared__ float rs[16 * 64], rs2[16 * 64];
    int b = blockIdx.y;
    int n0 = blockIdx.x * 64;
    int tid = threadIdx.x;
    int cg = tid & 15, rg = tid >> 4;
    int n = n0 + cg * 4;
    const float* p = x + (size_t)b * TT * NN + n;
    __half* ph = g_hi + (size_t)b * TT * NN + n;
    __half* pl = g_lo + (size_t)b * TT * NN + n;

    float s[4] = {}, q[4] = {};
#pragma unroll 4
    for (int it = 0; it < 64; ++it) {
        int t = rg + 16 * it;
        float4 v = *(const float4*)(p + (size_t)t * NN);
        __half2 h01 = __float22half2_rn(make_float2(v.x, v.y));
        __half2 h23 = __float22half2_rn(make_float2(v.z, v.w));
        float2 c01 = __half22float2(h01);
        float2 c23 = __half22float2(h23);
        __half2 l01 = __float22half2_rn(make_float2(v.x - c01.x, v.y - c01.y));
        __half2 l23 = __float22half2_rn(make_float2(v.z - c23.x, v.w - c23.y));
        *(uint2*)(ph + (size_t)t * NN) = make_uint2(h2u(h01), h2u(h23));
        *(uint2*)(pl + (size_t)t * NN) = make_uint2(h2u(l01), h2u(l23));
        s[0] += v.x; q[0] = fmaf(v.x, v.x, q[0]);
        s[1] += v.y; q[1] = fmaf(v.y, v.y, q[1]);
        s[2] += v.z; q[2] = fmaf(v.z, v.z, q[2]);
        s[3] += v.w; q[3] = fmaf(v.w, v.w, q[3]);
    }
    *(float4*)(rs + rg * 64 + cg * 4) = *(float4*)s;
    *(float4*)(rs2 + rg * 64 + cg * 4) = *(float4*)q;
    __syncthreads();
    if (tid < 64) {
        float S = 0.f, S2 = 0.f;
#pragma unroll
        for (int k = 0; k < 16; ++k) {
            S += rs[k * 64 + tid];
            S2 += rs2[k * 64 + tid];
        }
        float mu = S * (1.0f / TT);
        float Gnn = S2 - S * mu;
        g_mu[b * NN + n0 + tid] = mu;
        g_invd[b * NN + n0 + tid] = rsqrtf(fmaxf(Gnn, 1e-30f));
    }
}

// ---------------------------------------------------------------------------
// mma / ldmatrix / cp.async helpers
// ---------------------------------------------------------------------------
__device__ __forceinline__ void ldsm4t(uint32_t addr, uint32_t& r0, uint32_t& r1,
                                       uint32_t& r2, uint32_t& r3) {
    asm volatile(
        "ldmatrix.sync.aligned.m8n8.x4.trans.shared.b16 {%0,%1,%2,%3}, [%4];"
        : "=r"(r0), "=r"(r1), "=r"(r2), "=r"(r3)
        : "r"(addr));
}

__device__ __forceinline__ void mma_f32acc(float* d, const uint32_t* a,
                                           const uint32_t* b) {
    asm volatile(
        "mma.sync.aligned.m16n8k16.row.col.f32.f16.f16.f32 "
        "{%0,%1,%2,%3},{%4,%5,%6,%7},{%8,%9},{%0,%1,%2,%3};"
        : "+f"(d[0]), "+f"(d[1]), "+f"(d[2]), "+f"(d[3])
        : "r"(a[0]), "r"(a[1]), "r"(a[2]), "r"(a[3]), "r"(b[0]), "r"(b[1]));
}

__device__ __forceinline__ void mma_f16acc(uint32_t* d, const uint32_t* a,
                                           const uint32_t* b) {
    asm volatile(
        "mma.sync.aligned.m16n8k16.row.col.f16.f16.f16.f16 "
        "{%0,%1},{%2,%3,%4,%5},{%6,%7},{%0,%1};"
        : "+r"(d[0]), "+r"(d[1])
        : "r"(a[0]), "r"(a[1]), "r"(a[2]), "r"(a[3]), "r"(b[0]), "r"(b[1]));
}

__device__ __forceinline__ void cp16(uint32_t dst, const void* src) {
    asm volatile("cp.async.cg.shared.global [%0], [%1], 16;" ::"r"(dst),
                 "l"(src) : "memory");
}
#define CP_COMMIT() asm volatile("cp.async.commit_group;" ::: "memory")
#define CP_WAIT0() asm volatile("cp.async.wait_group 0;" ::: "memory")

// ---------------------------------------------------------------------------
// Kernel 2: tensor-core batched SYRK, BK=128, 2-stage cp.async,
// fragment double-buffering. 512 threads, 128x128 upper-tri tile pairs.
// ---------------------------------------------------------------------------
__global__ __launch_bounds__(512) void syrk_corr_tc(float* __restrict__ out) {
    extern __shared__ __half dynsm[];

    int b = blockIdx.y;
    int p = blockIdx.x;
    int i = 0, rem = p;
    while (rem >= NT - i) { rem -= NT - i; ++i; }
    int j = i + rem;
    bool diag = (i == j);
    int ni0 = i * 128;
    int nj0 = j * 128;

    int tid = threadIdx.x;
    int lane = tid & 31;
    int w = tid >> 5;
    int m_off = (w & 3) * 32;
    int n_off = (w >> 2) * 32;

    // ldmatrix per-lane bases (element offsets).
    int q = lane >> 3, r7 = lane & 7;
    int a_base = (r7 + (q >> 1) * 8) * PITCH + m_off + (q & 1) * 8;
    int b_base = (r7 + (q & 1) * 8) * PITCH + n_off + (q >> 1) * 8;

    // Loader: thread covers rows l_k + {0,32,64,96} of the 128-row chunk.
    int l_k = tid >> 4;        // 0..31
    int l_n8 = (tid & 15) * 8;

    const __half* gA = g_hi + (size_t)b * TT * NN + ni0 + l_n8;
    const __half* gBh = g_hi + (size_t)b * TT * NN + nj0 + l_n8;
    const __half* gBl = g_lo + (size_t)b * TT * NN + nj0 + l_n8;

    uint32_t smem_u = (uint32_t)__cvta_generic_to_shared(dynsm);
    uint32_t lofs[4];
#pragma unroll
    for (int rr = 0; rr < 4; ++rr)
        lofs[rr] = (uint32_t)(((l_k + 32 * rr) * PITCH + l_n8) * 2);

    float acc[2][4][4] = {};
    uint32_t corr[2][4][2];
#pragma unroll
    for (int mt = 0; mt < 2; ++mt)
#pragma unroll
        for (int nt = 0; nt < 4; ++nt) corr[mt][nt][0] = corr[mt][nt][1] = 0u;

    // prologue: chunk 0 into slot 0
    {
        uint32_t st = smem_u;
#pragma unroll
        for (int rr = 0; rr < 4; ++rr) {
            size_t g = (size_t)(l_k + 32 * rr) * NN;
            cp16(st + lofs[rr], gA + g);
            if (!diag) cp16(st + COMP_E * 2 + lofs[rr], gBh + g);
            cp16(st + 2 * COMP_E * 2 + lofs[rr], gBl + g);
        }
        CP_COMMIT();
    }

    uint32_t ahi[2][2][4], bhi[2][4][2], blo[2][4][2];

#define LDFRAGS(BUF, KS)                                                      \
    do {                                                                      \
        uint32_t kofs = (uint32_t)((KS) * 16 * PITCH * 2);                    \
        uint32_t a_off = (uint32_t)(a_base * 2) + kofs;                       \
        uint32_t b_off = (uint32_t)(b_base * 2) + kofs;                       \
        ldsm4t(sAhi + a_off, ahi[BUF][0][0], ahi[BUF][0][1], ahi[BUF][0][2],  \
               ahi[BUF][0][3]);                                               \
        ldsm4t(sAhi + a_off + 32, ahi[BUF][1][0], ahi[BUF][1][1],             \
               ahi[BUF][1][2], ahi[BUF][1][3]);                               \
        ldsm4t(sBhi + b_off, bhi[BUF][0][0], bhi[BUF][0][1], bhi[BUF][1][0],  \
               bhi[BUF][1][1]);                                               \
        ldsm4t(sBhi + b_off + 32, bhi[BUF][2][0], bhi[BUF][2][1],             \
               bhi[BUF][3][0], bhi[BUF][3][1]);                               \
        ldsm4t(sBlo + b_off, blo[BUF][0][0], blo[BUF][0][1], blo[BUF][1][0],  \
               blo[BUF][1][1]);                                               \
        ldsm4t(sBlo + b_off + 32, blo[BUF][2][0], blo[BUF][2][1],             \
               blo[BUF][3][0], blo[BUF][3][1]);                               \
    } while (0)

    for (int c = 0; c < NCHUNK; ++c) {
        CP_WAIT0();       // chunk c's cp group complete
        __syncthreads();  // all warps past chunk c-1's mma (other slot free)

        // issue chunk c+1 into the other slot; overlaps this chunk's mma
        if (c + 1 < NCHUNK) {
            uint32_t st = smem_u + (uint32_t)(((c + 1) & 1) * STAGE_E * 2);
#pragma unroll
            for (int rr = 0; rr < 4; ++rr) {
                size_t g = (size_t)((c + 1) * BK + l_k + 32 * rr) * NN;
                cp16(st + lofs[rr], gA + g);
                if (!diag) cp16(st + COMP_E * 2 + lofs[rr], gBh + g);
                cp16(st + 2 * COMP_E * 2 + lofs[rr], gBl + g);
            }
        }
        CP_COMMIT();

        uint32_t sAhi = smem_u + (uint32_t)((c & 1) * STAGE_E * 2);
        uint32_t sBhi = diag ? sAhi : sAhi + COMP_E * 2;
        uint32_t sBlo = sAhi + 2 * COMP_E * 2;

        LDFRAGS(0, 0);
#pragma unroll
        for (int ks = 0; ks < 8; ++ks) {
            int cb = ks & 1;
            if (ks < 7) {
                if (cb == 0) LDFRAGS(1, ks + 1);
                else         LDFRAGS(0, ks + 1);
            }
#pragma unroll
            for (int mt = 0; mt < 2; ++mt)
#pragma unroll
                for (int nt = 0; nt < 4; ++nt)
                    mma_f32acc(acc[mt][nt], ahi[cb][mt], bhi[cb][nt]);
#pragma unroll
            for (int mt = 0; mt < 2; ++mt)
#pragma unroll
                for (int nt = 0; nt < 4; ++nt)
                    mma_f16acc(corr[mt][nt], ahi[cb][mt], blo[cb][nt]);
        }
    }
#undef LDFRAGS

    // fold fp16 corrections into fp32 accumulators
#pragma unroll
    for (int mt = 0; mt < 2; ++mt)
#pragma unroll
        for (int nt = 0; nt < 4; ++nt) {
            float2 c0 = __half22float2(
                *reinterpret_cast<__half2*>(&corr[mt][nt][0]));
            float2 c1 = __half22float2(
                *reinterpret_cast<__half2*>(&corr[mt][nt][1]));
            acc[mt][nt][0] += c0.x;
            acc[mt][nt][1] += c0.y;
            acc[mt][nt][2] += c1.x;
            acc[mt][nt][3] += c1.y;
        }

    // ----------------------- epilogue -----------------------
    const float* mu_b = g_mu + b * NN;
    const float* id_b = g_invd + b * NN;
    float* ob = out + (size_t)b * NN * NN;

#pragma unroll
    for (int mt = 0; mt < 2; ++mt) {
#pragma unroll
        for (int half = 0; half < 2; ++half) {
            int R = m_off + mt * 16 + (lane >> 2) + half * 8;
            int n = ni0 + R;
            float mun = mu_b[n];
            float idn = id_b[n];
#pragma unroll
            for (int nt = 0; nt < 4; ++nt) {
                int C = n_off + nt * 8 + (lane & 3) * 2;
                int m = nj0 + C;
                float mum0 = mu_b[m], mum1 = mu_b[m + 1];
                float idm0 = id_b[m], idm1 = id_b[m + 1];
                float g0 = acc[mt][nt][half * 2 + 0] - (float)TT * mun * mum0;
                float g1 = acc[mt][nt][half * 2 + 1] - (float)TT * mun * mum1;
                float c0 = fminf(1.f, fmaxf(-1.f, g0 * idn * idm0));
                float c1 = fminf(1.f, fmaxf(-1.f, g1 * idn * idm1));
                *reinterpret_cast<float2*>(&ob[(size_t)n * NN + m]) =
                    make_float2(c0, c1);
                ob[(size_t)m * NN + n] = c0;  // mirror
                ob[(size_t)(m + 1) * NN + n] = c1;
            }
        }
    }
}

// ---------------------------------------------------------------------------
extern "C" void kernel_launch(void* const* d_in, const int* in_sizes, int n_in,
                              void* d_out, int out_size) {
    const float* x = (const float*)d_in[0];
    float* out = (float*)d_out;

    cudaFuncSetAttribute(syrk_corr_tc, cudaFuncAttributeMaxDynamicSharedMemorySize,
                         DYN_B);

    {
        dim3 grid(NN / 64, BB);
        convert_stats<<<grid, 256>>>(x);
    }
    {
        dim3 grid(NPAIRS_TC, BB);
        syrk_corr_tc<<<grid, 512, DYN_B>>>(out);
    }
}

// round 16
// speedup vs baseline: 1.6553x; 1.6553x over previous
#include <cuda_runtime.h>
#include <cuda_fp16.h>
#include <cstdint>

// B=64, C=1, T=1024, N=512.
// corr[b] = normalized column-centered Gram of x[b,0] (T x N). BN cancels.
// G[n,m] = sum_t x[t,n]x[t,m] - T*mu[n]*mu[m];  corr = clip(G*invd_n*invd_m)
// R16: pure-hi fp16 Gram: G ~= h h^T only (h = rn(x)). Measured: each dropped
// cross term (h l^T / l h^T) costs ~1.2e-4 rel err -> total ~2.4e-4 < 1e-3.
// Halves HMMA count vs R14 and removes the lo stream everywhere.
// Structure: BK=64, 2-stage cp.async ring, fragment double-buffering.

#define BB 64
#define TT 1024
#define NN 512
#define NT 4            // 512/128 tiles
#define NPAIRS_TC 10    // upper-triangular tile pairs
#define BK 64           // K-chunk
#define NCHUNK (TT / BK)           // 16
#define PITCH 136       // fp16 per smem row (conflict-free for ldsm)
#define COMP_E (BK * PITCH)        // 8704 elements per component
#define STAGE_E (2 * COMP_E)       // Ahi, Bhi
#define NSTAGE 2
#define DYN_B (NSTAGE * STAGE_E * 2)   // 69632 bytes

__device__ __half g_hi[(size_t)BB * TT * NN];
__device__ float g_mu[BB * NN];
__device__ float g_invd[BB * NN];

__device__ __forceinline__ uint32_t h2u(__half2 h) {
    return *reinterpret_cast<uint32_t*>(&h);
}

// ---------------------------------------------------------------------------
// Kernel 1: convert fp32 -> hi fp16 + column stats. Pure streaming (201 MB).
// ---------------------------------------------------------------------------
__global__ __launch_bounds__(256) void convert_stats(const float* __restrict__ x) {
    __shared__ float rs[16 * 64], rs2[16 * 64];
    int b = blockIdx.y;
    int n0 = blockIdx.x * 64;
    int tid = threadIdx.x;
    int cg = tid & 15, rg = tid >> 4;
    int n = n0 + cg * 4;
    const float* p = x + (size_t)b * TT * NN + n;
    __half* ph = g_hi + (size_t)b * TT * NN + n;

    float s[4] = {}, q[4] = {};
#pragma unroll 4
    for (int it = 0; it < 64; ++it) {
        int t = rg + 16 * it;
        float4 v = *(const float4*)(p + (size_t)t * NN);
        __half2 h01 = __float22half2_rn(make_float2(v.x, v.y));
        __half2 h23 = __float22half2_rn(make_float2(v.z, v.w));
        *(uint2*)(ph + (size_t)t * NN) = make_uint2(h2u(h01), h2u(h23));
        s[0] += v.x; q[0] = fmaf(v.x, v.x, q[0]);
        s[1] += v.y; q[1] = fmaf(v.y, v.y, q[1]);
        s[2] += v.z; q[2] = fmaf(v.z, v.z, q[2]);
        s[3] += v.w; q[3] = fmaf(v.w, v.w, q[3]);
    }
    *(float4*)(rs + rg * 64 + cg * 4) = *(float4*)s;
    *(float4*)(rs2 + rg * 64 + cg * 4) = *(float4*)q;
    __syncthreads();
    if (tid < 64) {
        float S = 0.f, S2 = 0.f;
#pragma unroll
        for (int k = 0; k < 16; ++k) {
            S += rs[k * 64 + tid];
            S2 += rs2[k * 64 + tid];
        }
        float mu = S * (1.0f / TT);
        float Gnn = S2 - S * mu;
        g_mu[b * NN + n0 + tid] = mu;
        g_invd[b * NN + n0 + tid] = rsqrtf(fmaxf(Gnn, 1e-30f));
    }
}

// ---------------------------------------------------------------------------
// mma / ldmatrix / cp.async helpers
// ---------------------------------------------------------------------------
__device__ __forceinline__ void ldsm4t(uint32_t addr, uint32_t& r0, uint32_t& r1,
                                       uint32_t& r2, uint32_t& r3) {
    asm volatile(
        "ldmatrix.sync.aligned.m8n8.x4.trans.shared.b16 {%0,%1,%2,%3}, [%4];"
        : "=r"(r0), "=r"(r1), "=r"(r2), "=r"(r3)
        : "r"(addr));
}

__device__ __forceinline__ void mma_f32acc(float* d, const uint32_t* a,
                                           const uint32_t* b) {
    asm volatile(
        "mma.sync.aligned.m16n8k16.row.col.f32.f16.f16.f32 "
        "{%0,%1,%2,%3},{%4,%5,%6,%7},{%8,%9},{%0,%1,%2,%3};"
        : "+f"(d[0]), "+f"(d[1]), "+f"(d[2]), "+f"(d[3])
        : "r"(a[0]), "r"(a[1]), "r"(a[2]), "r"(a[3]), "r"(b[0]), "r"(b[1]));
}

__device__ __forceinline__ void cp16(uint32_t dst, const void* src) {
    asm volatile("cp.async.cg.shared.global [%0], [%1], 16;" ::"r"(dst),
                 "l"(src) : "memory");
}
#define CP_COMMIT() asm volatile("cp.async.commit_group;" ::: "memory")
#define CP_WAIT0() asm volatile("cp.async.wait_group 0;" ::: "memory")

// ---------------------------------------------------------------------------
// Kernel 2: tensor-core batched SYRK (hi only), BK=64, 2-stage cp.async,
// fragment double-buffering. 512 threads, 128x128 upper-tri tile pairs.
// ---------------------------------------------------------------------------
__global__ __launch_bounds__(512) void syrk_corr_tc(float* __restrict__ out) {
    extern __shared__ __half dynsm[];

    int b = blockIdx.y;
    int p = blockIdx.x;
    int i = 0, rem = p;
    while (rem >= NT - i) { rem -= NT - i; ++i; }
    int j = i + rem;
    bool diag = (i == j);
    int ni0 = i * 128;
    int nj0 = j * 128;

    int tid = threadIdx.x;
    int lane = tid & 31;
    int w = tid >> 5;
    int m_off = (w & 3) * 32;
    int n_off = (w >> 2) * 32;

    // ldmatrix per-lane bases (element offsets).
    int q = lane >> 3, r7 = lane & 7;
    int a_base = (r7 + (q >> 1) * 8) * PITCH + m_off + (q & 1) * 8;
    int b_base = (r7 + (q & 1) * 8) * PITCH + n_off + (q >> 1) * 8;

    // Loader: thread covers rows l_k and l_k+32 of the 64-row chunk.
    int l_k = tid >> 4;        // 0..31
    int l_n8 = (tid & 15) * 8;

    const __half* gA = g_hi + (size_t)b * TT * NN + ni0 + l_n8;
    const __half* gB = g_hi + (size_t)b * TT * NN + nj0 + l_n8;

    uint32_t smem_u = (uint32_t)__cvta_generic_to_shared(dynsm);
    uint32_t o0 = (uint32_t)((l_k * PITCH + l_n8) * 2);
    uint32_t o1 = (uint32_t)(((l_k + 32) * PITCH + l_n8) * 2);

    float acc[2][4][4] = {};

    // prologue: chunk 0 into slot 0
    {
        uint32_t st = smem_u;
        size_t gg0 = (size_t)l_k * NN;
        size_t gg1 = (size_t)(l_k + 32) * NN;
        cp16(st + o0, gA + gg0);
        cp16(st + o1, gA + gg1);
        if (!diag) {
            cp16(st + COMP_E * 2 + o0, gB + gg0);
            cp16(st + COMP_E * 2 + o1, gB + gg1);
        }
        CP_COMMIT();
    }

    uint32_t ahi[2][2][4], bhi[2][4][2];

#define LDFRAGS(BUF, KS)                                                      \
    do {                                                                      \
        uint32_t kofs = (uint32_t)((KS) * 16 * PITCH * 2);                    \
        uint32_t a_off = (uint32_t)(a_base * 2) + kofs;                       \
        uint32_t b_off = (uint32_t)(b_base * 2) + kofs;                       \
        ldsm4t(sAhi + a_off, ahi[BUF][0][0], ahi[BUF][0][1], ahi[BUF][0][2],  \
               ahi[BUF][0][3]);                                               \
        ldsm4t(sAhi + a_off + 32, ahi[BUF][1][0], ahi[BUF][1][1],             \
               ahi[BUF][1][2], ahi[BUF][1][3]);                               \
        ldsm4t(sBhi + b_off, bhi[BUF][0][0], bhi[BUF][0][1], bhi[BUF][1][0],  \
               bhi[BUF][1][1]);                                               \
        ldsm4t(sBhi + b_off + 32, bhi[BUF][2][0], bhi[BUF][2][1],             \
               bhi[BUF][3][0], bhi[BUF][3][1]);                               \
    } while (0)

    for (int c = 0; c < NCHUNK; ++c) {
        CP_WAIT0();       // chunk c's cp group complete
        __syncthreads();  // all warps past chunk c-1's mma (other slot free)

        // issue chunk c+1 into the other slot; overlaps this chunk's mma
        if (c + 1 < NCHUNK) {
            uint32_t st = smem_u + (uint32_t)(((c + 1) & 1) * STAGE_E * 2);
            size_t gg0 = (size_t)((c + 1) * BK + l_k) * NN;
            size_t gg1 = (size_t)((c + 1) * BK + l_k + 32) * NN;
            cp16(st + o0, gA + gg0);
            cp16(st + o1, gA + gg1);
            if (!diag) {
                cp16(st + COMP_E * 2 + o0, gB + gg0);
                cp16(st + COMP_E * 2 + o1, gB + gg1);
            }
        }
        CP_COMMIT();

        uint32_t sAhi = smem_u + (uint32_t)((c & 1) * STAGE_E * 2);
        uint32_t sBhi = diag ? sAhi : sAhi + COMP_E * 2;

        LDFRAGS(0, 0);
#pragma unroll
        for (int ks = 0; ks < 4; ++ks) {
            int cb = ks & 1;
            if (ks < 3) {
                if (cb == 0) LDFRAGS(1, ks + 1);
                else         LDFRAGS(0, ks + 1);
            }
#pragma unroll
            for (int mt = 0; mt < 2; ++mt)
#pragma unroll
                for (int nt = 0; nt < 4; ++nt)
                    mma_f32acc(acc[mt][nt], ahi[cb][mt], bhi[cb][nt]);
        }
    }
#undef LDFRAGS

    // ----------------------- epilogue -----------------------
    const float* mu_b = g_mu + b * NN;
    const float* id_b = g_invd + b * NN;
    float* ob = out + (size_t)b * NN * NN;

#pragma unroll
    for (int mt = 0; mt < 2; ++mt) {
#pragma unroll
        for (int half = 0; half < 2; ++half) {
            int R = m_off + mt * 16 + (lane >> 2) + half * 8;
            int n = ni0 + R;
            float mun = mu_b[n];
            float idn = id_b[n];
#pragma unroll
            for (int nt = 0; nt < 4; ++nt) {
                int C = n_off + nt * 8 + (lane & 3) * 2;
                int m = nj0 + C;
                float mum0 = mu_b[m], mum1 = mu_b[m + 1];
                float idm0 = id_b[m], idm1 = id_b[m + 1];
                float g0 = acc[mt][nt][half * 2 + 0] - (float)TT * mun * mum0;
                float g1 = acc[mt][nt][half * 2 + 1] - (float)TT * mun * mum1;
                float c0 = fminf(1.f, fmaxf(-1.f, g0 * idn * idm0));
                float c1 = fminf(1.f, fmaxf(-1.f, g1 * idn * idm1));
                *reinterpret_cast<float2*>(&ob[(size_t)n * NN + m]) =
                    make_float2(c0, c1);
                ob[(size_t)m * NN + n] = c0;  // mirror
                ob[(size_t)(m + 1) * NN + n] = c1;
            }
        }
    }
}

// ---------------------------------------------------------------------------
extern "C" void kernel_launch(void* const* d_in, const int* in_sizes, int n_in,
                              void* d_out, int out_size) {
    const float* x = (const float*)d_in[0];
    float* out = (float*)d_out;

    cudaFuncSetAttribute(syrk_corr_tc, cudaFuncAttributeMaxDynamicSharedMemorySize,
                         DYN_B);

    {
        dim3 grid(NN / 64, BB);
        convert_stats<<<grid, 256>>>(x);
    }
    {
        dim3 grid(NPAIRS_TC, BB);
        syrk_corr_tc<<<grid, 512, DYN_B>>>(out);
    }
}

// round 17
// speedup vs baseline: 1.7380x; 1.0500x over previous
#include <cuda_runtime.h>
#include <cuda_fp16.h>
#include <cstdint>

// B=64, C=1, T=1024, N=512.
// corr[b] = normalized column-centered Gram of x[b,0] (T x N). BN cancels.
// G[n,m] = sum_t x[t,n]x[t,m] - T*mu[n]*mu[m];  corr = clip(G*invd_n*invd_m)
// Pure-hi fp16 Gram (G ~= h h^T, h = rn(x)); measured rel_err 1.7e-4.
// R17: SYRK re-tiled to 256 threads / 8 warps / 64x32 warp tiles (-25% ldsm
// traffic, 2.7 MMA/ldsm), 2 CTAs/SM, diag warp-skip. Convert unchanged.

#define BB 64
#define TT 1024
#define NN 512
#define NT 4            // 512/128 tiles
#define NPAIRS_TC 10    // upper-triangular tile pairs
#define BK 64           // K-chunk
#define NCHUNK (TT / BK)           // 16
#define PITCH 136       // fp16 per smem row (conflict-free for ldsm)
#define COMP_E (BK * PITCH)        // 8704 elements per component
#define STAGE_E (2 * COMP_E)       // Ahi, Bhi
#define NSTAGE 2
#define DYN_B (NSTAGE * STAGE_E * 2)   // 69632 bytes

__device__ __half g_hi[(size_t)BB * TT * NN];
__device__ float g_mu[BB * NN];
__device__ float g_invd[BB * NN];

__device__ __forceinline__ uint32_t h2u(__half2 h) {
    return *reinterpret_cast<uint32_t*>(&h);
}

// ---------------------------------------------------------------------------
// Kernel 1: convert fp32 -> hi fp16 + column stats. Pure streaming (201 MB).
// ---------------------------------------------------------------------------
__global__ __launch_bounds__(256) void convert_stats(const float* __restrict__ x) {
    __shared__ float rs[16 * 64], rs2[16 * 64];
    int b = blockIdx.y;
    int n0 = blockIdx.x * 64;
    int tid = threadIdx.x;
    int cg = tid & 15, rg = tid >> 4;
    int n = n0 + cg * 4;
    const float* p = x + (size_t)b * TT * NN + n;
    __half* ph = g_hi + (size_t)b * TT * NN + n;

    float s[4] = {}, q[4] = {};
#pragma unroll 4
    for (int it = 0; it < 64; ++it) {
        int t = rg + 16 * it;
        float4 v = *(const float4*)(p + (size_t)t * NN);
        __half2 h01 = __float22half2_rn(make_float2(v.x, v.y));
        __half2 h23 = __float22half2_rn(make_float2(v.z, v.w));
        *(uint2*)(ph + (size_t)t * NN) = make_uint2(h2u(h01), h2u(h23));
        s[0] += v.x; q[0] = fmaf(v.x, v.x, q[0]);
        s[1] += v.y; q[1] = fmaf(v.y, v.y, q[1]);
        s[2] += v.z; q[2] = fmaf(v.z, v.z, q[2]);
        s[3] += v.w; q[3] = fmaf(v.w, v.w, q[3]);
    }
    *(float4*)(rs + rg * 64 + cg * 4) = *(float4*)s;
    *(float4*)(rs2 + rg * 64 + cg * 4) = *(float4*)q;
    __syncthreads();
    if (tid < 64) {
        float S = 0.f, S2 = 0.f;
#pragma unroll
        for (int k = 0; k < 16; ++k) {
            S += rs[k * 64 + tid];
            S2 += rs2[k * 64 + tid];
        }
        float mu = S * (1.0f / TT);
        float Gnn = S2 - S * mu;
        g_mu[b * NN + n0 + tid] = mu;
        g_invd[b * NN + n0 + tid] = rsqrtf(fmaxf(Gnn, 1e-30f));
    }
}

// ---------------------------------------------------------------------------
// mma / ldmatrix / cp.async helpers
// ---------------------------------------------------------------------------
__device__ __forceinline__ void ldsm4t(uint32_t addr, uint32_t& r0, uint32_t& r1,
                                       uint32_t& r2, uint32_t& r3) {
    asm volatile(
        "ldmatrix.sync.aligned.m8n8.x4.trans.shared.b16 {%0,%1,%2,%3}, [%4];"
        : "=r"(r0), "=r"(r1), "=r"(r2), "=r"(r3)
        : "r"(addr));
}

__device__ __forceinline__ void mma_f32acc(float* d, const uint32_t* a,
                                           const uint32_t* b) {
    asm volatile(
        "mma.sync.aligned.m16n8k16.row.col.f32.f16.f16.f32 "
        "{%0,%1,%2,%3},{%4,%5,%6,%7},{%8,%9},{%0,%1,%2,%3};"
        : "+f"(d[0]), "+f"(d[1]), "+f"(d[2]), "+f"(d[3])
        : "r"(a[0]), "r"(a[1]), "r"(a[2]), "r"(a[3]), "r"(b[0]), "r"(b[1]));
}

__device__ __forceinline__ void cp16(uint32_t dst, const void* src) {
    asm volatile("cp.async.cg.shared.global [%0], [%1], 16;" ::"r"(dst),
                 "l"(src) : "memory");
}
#define CP_COMMIT() asm volatile("cp.async.commit_group;" ::: "memory")
#define CP_WAIT0() asm volatile("cp.async.wait_group 0;" ::: "memory")

// ---------------------------------------------------------------------------
// Kernel 2: tensor-core batched SYRK (hi only), 256 threads, 8 warps,
// warp tile 64x32 (R4 fragment mapping), BK=64, 2-stage cp.async,
// 2 CTAs/SM. Diag CTAs: B aliases A; warps (64,0)/(64,32) skip (mirror-covered).
// ---------------------------------------------------------------------------
__global__ __launch_bounds__(256, 2) void syrk_corr_tc(float* __restrict__ out) {
    extern __shared__ __half dynsm[];

    int b = blockIdx.y;
    int p = blockIdx.x;
    int i = 0, rem = p;
    while (rem >= NT - i) { rem -= NT - i; ++i; }
    int j = i + rem;
    bool diag = (i == j);
    int ni0 = i * 128;
    int nj0 = j * 128;

    int tid = threadIdx.x;
    int lane = tid & 31;
    int w = tid >> 5;
    int m_off = (w & 1) * 64;   // output-row offset within tile
    int n_off = (w >> 1) * 32;  // output-col offset within tile
    bool wskip = diag && (m_off > n_off);  // mirror-covered warps on diag

    // ldmatrix per-lane bases (element offsets) — R4 verified mapping.
    int q = lane >> 3, r7 = lane & 7;
    int a_base = (r7 + (q >> 1) * 8) * PITCH + m_off + (q & 1) * 8;
    int b_base = (r7 + (q & 1) * 8) * PITCH + n_off + (q >> 1) * 8;

    // Loader: 16 threads per row (16B each); thread covers rows l_k+{0,16,32,48}.
    int l_k = tid >> 4;        // 0..15
    int l_n8 = (tid & 15) * 8;

    const __half* gA = g_hi + (size_t)b * TT * NN + ni0 + l_n8;
    const __half* gB = g_hi + (size_t)b * TT * NN + nj0 + l_n8;

    uint32_t smem_u = (uint32_t)__cvta_generic_to_shared(dynsm);
    uint32_t lofs[4];
#pragma unroll
    for (int rr = 0; rr < 4; ++rr)
        lofs[rr] = (uint32_t)(((l_k + 16 * rr) * PITCH + l_n8) * 2);

    float acc[2][4][2][4] = {};  // [mt-pair][nt][mt-half][4] == acc[4 mt][4 nt][4]
    float(*accf)[4][4] = reinterpret_cast<float(*)[4][4]>(acc);  // [mt][nt][4]

    // prologue: chunk 0 into slot 0
    {
        uint32_t st = smem_u;
#pragma unroll
        for (int rr = 0; rr < 4; ++rr) {
            size_t g = (size_t)(l_k + 16 * rr) * NN;
            cp16(st + lofs[rr], gA + g);
            if (!diag) cp16(st + COMP_E * 2 + lofs[rr], gB + g);
        }
        CP_COMMIT();
    }

    for (int c = 0; c < NCHUNK; ++c) {
        CP_WAIT0();       // chunk c's cp group complete
        __syncthreads();  // all warps past chunk c-1's mma (other slot free)

        // issue chunk c+1 into the other slot; overlaps this chunk's mma
        if (c + 1 < NCHUNK) {
            uint32_t st = smem_u + (uint32_t)(((c + 1) & 1) * STAGE_E * 2);
#pragma unroll
            for (int rr = 0; rr < 4; ++rr) {
                size_t g = (size_t)((c + 1) * BK + l_k + 16 * rr) * NN;
                cp16(st + lofs[rr], gA + g);
                if (!diag) cp16(st + COMP_E * 2 + lofs[rr], gB + g);
            }
        }
        CP_COMMIT();

        if (!wskip) {
            uint32_t sAhi = smem_u + (uint32_t)((c & 1) * STAGE_E * 2);
            uint32_t sBhi = diag ? sAhi : sAhi + COMP_E * 2;

#pragma unroll
            for (int ks = 0; ks < 4; ++ks) {
                uint32_t kofs = (uint32_t)(ks * 16 * PITCH * 2);
                uint32_t a_off = (uint32_t)(a_base * 2) + kofs;
                uint32_t b_off = (uint32_t)(b_base * 2) + kofs;

                uint32_t ahi[4][4], bhi[4][2];
#pragma unroll
                for (int mt = 0; mt < 4; ++mt)
                    ldsm4t(sAhi + a_off + mt * 32, ahi[mt][0], ahi[mt][1],
                           ahi[mt][2], ahi[mt][3]);
#pragma unroll
                for (int nb = 0; nb < 2; ++nb)
                    ldsm4t(sBhi + b_off + nb * 32, bhi[nb * 2][0],
                           bhi[nb * 2][1], bhi[nb * 2 + 1][0],
                           bhi[nb * 2 + 1][1]);
#pragma unroll
                for (int mt = 0; mt < 4; ++mt)
#pragma unroll
                    for (int nt = 0; nt < 4; ++nt)
                        mma_f32acc(accf[mt][nt], ahi[mt], bhi[nt]);
            }
        }
    }

    // ----------------------- epilogue -----------------------
    if (!wskip) {
        const float* mu_b = g_mu + b * NN;
        const float* id_b = g_invd + b * NN;
        float* ob = out + (size_t)b * NN * NN;

#pragma unroll
        for (int mt = 0; mt < 4; ++mt) {
#pragma unroll
            for (int half = 0; half < 2; ++half) {
                int R = m_off + mt * 16 + (lane >> 2) + half * 8;
                int n = ni0 + R;
                float mun = mu_b[n];
                float idn = id_b[n];
#pragma unroll
                for (int nt = 0; nt < 4; ++nt) {
                    int C = n_off + nt * 8 + (lane & 3) * 2;
                    int m = nj0 + C;
                    float mum0 = mu_b[m], mum1 = mu_b[m + 1];
                    float idm0 = id_b[m], idm1 = id_b[m + 1];
                    float g0 = accf[mt][nt][half * 2 + 0] - (float)TT * mun * mum0;
                    float g1 = accf[mt][nt][half * 2 + 1] - (float)TT * mun * mum1;
                    float c0 = fminf(1.f, fmaxf(-1.f, g0 * idn * idm0));
                    float c1 = fminf(1.f, fmaxf(-1.f, g1 * idn * idm1));
                    *reinterpret_cast<float2*>(&ob[(size_t)n * NN + m]) =
                        make_float2(c0, c1);
                    ob[(size_t)m * NN + n] = c0;  // mirror
                    ob[(size_t)(m + 1) * NN + n] = c1;
                }
            }
        }
    }
}

// ---------------------------------------------------------------------------
extern "C" void kernel_launch(void* const* d_in, const int* in_sizes, int n_in,
                              void* d_out, int out_size) {
    const float* x = (const float*)d_in[0];
    float* out = (float*)d_out;

    cudaFuncSetAttribute(syrk_corr_tc, cudaFuncAttributeMaxDynamicSharedMemorySize,
                         DYN_B);

    {
        dim3 grid(NN / 64, BB);
        convert_stats<<<grid, 256>>>(x);
    }
    {
        dim3 grid(NPAIRS_TC, BB);
        syrk_corr_tc<<<grid, 256, DYN_B>>>(out);
    }
}